// round 10
// baseline (speedup 1.0000x reference)
#include <cuda_runtime.h>

#define NH 8
#define DD 1024
#define MM 2048
#define PIX4 12288           // 128*128*3 / 4
#define MSLICE 128           // m per wsum tile
#define XTW 64               // float4 columns per wsum tile
#define XT (PIX4/XTW)        // 192
#define NTILES (XT*(MM/MSLICE))   // 192*16 = 3072
#define PGRID 444            // prep grid: 148x3, all-resident (grid barriers!)
#define WGRID 444            // wsum grid: fewer blocks -> smaller tile tail
#define NWARPS (PGRID*8)

#define STAGES 8
#define SROWS 4                          // m-rows per stage
#define ROWB (XTW*16)                    // 1024 bytes per row
#define STAGE_BYTES (SROWS*ROWB)         // 4096
#define NSTG (MSLICE/SROWS)              // 32 stages per tile
// dynamic smem layout (wsum)
#define SM_W2S   (STAGES*STAGE_BYTES)    // 32768
#define SM_MBAR  (SM_W2S + MSLICE*NH*8)  // 40960
#define SM_TILE  (SM_MBAR + STAGES*8)    // 41024
#define SM_TOTAL (SM_TILE + 16)

__device__ float g_q[NH*DD];
__device__ float g_t[NH*DD];
__device__ float g_c[NH];
__device__ float g_sums[NH];
__device__ float g_wt[MM*NH];   // unnormalized exp weights, transposed [m][h]
__device__ int   g_ctr;         // wsum ticket counter (reset by prep)
__device__ int   g_bar;         // prep grid barrier  (reset by wsum)

__device__ __forceinline__ unsigned long long pk2(float a, float b){
    unsigned long long r;
    asm("mov.b64 %0, {%1, %2};" : "=l"(r) : "f"(a), "f"(b));
    return r;
}
__device__ __forceinline__ void fma2(unsigned long long &acc, unsigned long long v, unsigned long long w){
    asm("fma.rn.f32x2 %0, %1, %2, %0;" : "+l"(acc) : "l"(v), "l"(w));
}
__device__ __forceinline__ void upk2(unsigned long long p, float &a, float &b){
    asm("mov.b64 {%0, %1}, %2;" : "=f"(a), "=f"(b) : "l"(p));
}
__device__ __forceinline__ unsigned int smem_u32(const void* p){
    unsigned int a;
    asm("{ .reg .u64 t; cvta.to.shared.u64 t, %1; cvt.u32.u64 %0, t; }" : "=r"(a) : "l"(p));
    return a;
}
__device__ __forceinline__ void mbar_wait(unsigned int mbar, unsigned int phase){
    asm volatile(
        "{\n\t.reg .pred P;\n"
        "LW%=:\n\t"
        "mbarrier.try_wait.parity.acquire.cta.shared::cta.b64 P, [%0], %1, 0x989680;\n\t"
        "@P bra LD%=;\n\t"
        "bra LW%=;\n"
        "LD%=:\n\t}"
        :: "r"(mbar), "r"(phase) : "memory");
}
// issue one stage: expect_tx + SROWS x 1KB 1D bulk copies (UBLKCP)
__device__ __forceinline__ void issue_stage(unsigned int dst, const float4* src, unsigned int mbar){
    asm volatile("mbarrier.arrive.expect_tx.shared.b64 _, [%0], %1;"
                 :: "r"(mbar), "r"((unsigned)STAGE_BYTES) : "memory");
    #pragma unroll
    for (int r = 0; r < SROWS; r++){
        asm volatile("cp.async.bulk.shared::cluster.global.mbarrier::complete_tx::bytes [%0], [%1], %2, [%3];"
            :: "r"(dst + r*ROWB), "l"(src + (size_t)r*PIX4), "r"((unsigned)ROWB), "r"(mbar)
            : "memory");
    }
}

// Grid barrier for prep: all PGRID blocks resident by construction.
__device__ __forceinline__ void grid_bar(int target) {
    __syncthreads();
    __threadfence();
    if (threadIdx.x == 0) {
        atomicAdd(&g_bar, 1);
        while (*(volatile int*)&g_bar < target) __nanosleep(64);
    }
    __syncthreads();
    __threadfence();
}

// ---------------------------------------------------------------------------
// Fused prologue: 3 phases, 2 grid barriers.
// ---------------------------------------------------------------------------
__global__ void __launch_bounds__(256, 3) prep_kernel(
        const float* __restrict__ Q,  const float* __restrict__ K,
        const float* __restrict__ WQ, const float* __restrict__ bQ,
        const float* __restrict__ WK, const float* __restrict__ bK,
        float4* __restrict__ out4) {
    __shared__ float4 ts4[NH*DD/4];   // 32 KB (phase C)
    __shared__ float ws[8][NH];
    int tid  = threadIdx.x;
    int gid  = blockIdx.x*256 + tid;
    int lane = tid & 31;
    int gwarp = gid >> 5;

    // ---- Phase A ----
    if (gid == 0) g_ctr = 0;
    if (gid < NH*DD) g_t[gid] = 0.f;
    if (gid < NH) { g_c[gid] = 0.f; g_sums[gid] = 0.f; }

    const float4* Q4 = (const float4*)Q;
    for (int task = gwarp; task < NH*DD; task += NWARPS) {
        int h = task >> 10, e = task & 1023;
        const float4* W4 = (const float4*)WQ + (size_t)h*(DD*DD/4) + (size_t)e*(DD/4);
        float acc = 0.f;
        #pragma unroll
        for (int i = 0; i < 8; i++) {
            float4 w = __ldcs(&W4[lane + i*32]);
            float4 q = Q4[lane + i*32];
            acc += w.x*q.x + w.y*q.y + w.z*q.z + w.w*q.w;
        }
        #pragma unroll
        for (int o = 16; o; o >>= 1) acc += __shfl_xor_sync(0xffffffffu, acc, o);
        if (lane == 0) g_q[h*DD + e] = acc + bQ[h*DD + e];
    }
    grid_bar(PGRID);

    // ---- Phase B ---- (2048 block-tasks: (h, e-chunk of 4))
    for (int t = blockIdx.x; t < 2048; t += PGRID) {
        int h = t >> 8, e0 = (t & 255) * 4;
        const float4* Wp = (const float4*)(WK + (size_t)h*DD*DD + (size_t)e0*DD) + tid;
        const float* qp = g_q + h*DD + e0;
        float4 acc = make_float4(0.f, 0.f, 0.f, 0.f);
        #pragma unroll
        for (int e = 0; e < 4; e++) {
            float qe = __ldcg(&qp[e]);
            float4 w = __ldcs(&Wp[(size_t)e*(DD/4)]);
            acc.x = fmaf(qe, w.x, acc.x);
            acc.y = fmaf(qe, w.y, acc.y);
            acc.z = fmaf(qe, w.z, acc.z);
            acc.w = fmaf(qe, w.w, acc.w);
        }
        float* p = &g_t[h*DD + tid*4];
        asm volatile("red.global.add.v4.f32 [%0], {%1, %2, %3, %4};"
                     :: "l"(p), "f"(acc.x), "f"(acc.y), "f"(acc.z), "f"(acc.w) : "memory");
    }
    if (blockIdx.x < 64 && tid < 32) {          // c[h] = q[h] . bK[h]
        int h = blockIdx.x >> 3, e0 = (blockIdx.x & 7) * 128;
        float v = 0.f;
        #pragma unroll
        for (int j = 0; j < 4; j++) {
            int e = e0 + lane + j*32;
            v = fmaf(__ldcg(&g_q[h*DD + e]), bK[h*DD + e], v);
        }
        #pragma unroll
        for (int o = 16; o; o >>= 1) v += __shfl_xor_sync(0xffffffffu, v, o);
        if (lane == 0) atomicAdd(&g_c[h], v);
    }
    grid_bar(2*PGRID);

    // ---- Phase C ----
    for (int idx = gid; idx < NH*PIX4; idx += PGRID*256)
        out4[idx] = make_float4(0.f, 0.f, 0.f, 0.f);

    if (blockIdx.x < 256) {
        for (int i = tid; i < NH*DD/4; i += 256) {
            const float* s = &g_t[i*4];
            ts4[i] = make_float4(__ldcg(s), __ldcg(s+1), __ldcg(s+2), __ldcg(s+3));
        }
        __syncthreads();

        int wid = tid >> 5;
        int m = blockIdx.x * 8 + wid;
        const float4* K4 = (const float4*)K + (size_t)m*(DD/4);
        float acc[NH];
        #pragma unroll
        for (int h = 0; h < NH; h++) acc[h] = 0.f;
        #pragma unroll
        for (int i = 0; i < 8; i++) {
            float4 k4 = K4[lane + i*32];
            #pragma unroll
            for (int h = 0; h < NH; h++) {
                float4 t4 = ts4[h*256 + lane + i*32];
                acc[h] += k4.x*t4.x + k4.y*t4.y + k4.z*t4.z + k4.w*t4.w;
            }
        }
        #pragma unroll
        for (int h = 0; h < NH; h++) {
            #pragma unroll
            for (int o = 16; o; o >>= 1) acc[h] += __shfl_xor_sync(0xffffffffu, acc[h], o);
        }
        if (lane == 0) {
            #pragma unroll
            for (int h = 0; h < NH; h++) {
                float w = expf((acc[h] + __ldcg(&g_c[h])) * (1.0f/1024.0f));
                g_wt[m*NH + h] = w;
                ws[wid][h] = w;
            }
        }
        __syncthreads();
        if (tid < NH) {
            float s = 0.f;
            #pragma unroll
            for (int w8 = 0; w8 < 8; w8++) s += ws[w8][tid];
            atomicAdd(&g_sums[tid], s);
        }
    }
}

// ---------------------------------------------------------------------------
// wsum: persistent tickets; 64KB tiles (128 m-rows x 64 cols); V staged via
// cp.async.bulk into an 8-stage smem ring; threads = 2 head-grps x 64 cols x
// 2 row-splits; LDS + f32x2 FMA; REDG.v4 output (merges row-split partials).
// ---------------------------------------------------------------------------
__global__ void __launch_bounds__(256, 3) wsum_kernel(const float* __restrict__ V,
                                                      float4* __restrict__ out4) {
    extern __shared__ char smem[];
    unsigned int sb = smem_u32(smem);
    int tid = threadIdx.x;
    int cid = tid & 63;          // float4 column within tile
    int grp = (tid >> 6) & 1;    // head group: heads [4g, 4g+4)
    int rid = tid >> 7;          // row split: rows {rid, rid+2} per stage
    if (blockIdx.x == 0 && tid == 0) g_bar = 0;   // reset prep barrier for next replay

    if (tid == 0) {
        #pragma unroll
        for (int i = 0; i < STAGES; i++)
            asm volatile("mbarrier.init.shared.b64 [%0], 1;" :: "r"(sb + SM_MBAR + i*8) : "memory");
        asm volatile("fence.proxy.async.shared::cta;" ::: "memory");
    }
    __syncthreads();

    unsigned long long* w2s = (unsigned long long*)(smem + SM_W2S);
    int* s_tile = (int*)(smem + SM_TILE);
    int sc = 0;   // absolute stage counter -> slot/parity

    for (;;) {
        if (tid == 0) *s_tile = atomicAdd(&g_ctr, 1);
        __syncthreads();
        int t = *s_tile;
        if (t >= NTILES) break;
        int s  = t / XT;
        int xb = t - s*XT;
        int m0 = s * MSLICE;

        // kick the TMA pipeline FIRST (independent of weights), then fill w2s
        const float4* src = (const float4*)V + (size_t)m0*PIX4 + xb*XTW;
        if (tid == 0) {
            #pragma unroll
            for (int j = 0; j < STAGES; j++)
                issue_stage(sb + ((sc + j) & (STAGES-1))*STAGE_BYTES,
                            src + (size_t)j*SROWS*PIX4,
                            sb + SM_MBAR + ((sc + j) & (STAGES-1))*8);
        }

        for (int i = tid; i < MSLICE*NH; i += 256) {
            float w = __fdividef(g_wt[m0*NH + i], g_sums[i & 7]);
            w2s[i] = pk2(w, w);
        }
        __syncthreads();

        unsigned long long a0[4], a1[4];
        #pragma unroll
        for (int i = 0; i < 4; i++) { a0[i] = 0ull; a1[i] = 0ull; }

        #pragma unroll 1
        for (int j = 0; j < NSTG; j++) {
            int slot = (sc + j) & (STAGES-1);
            unsigned int ph = ((unsigned)(sc + j) >> 3) & 1;
            mbar_wait(sb + SM_MBAR + slot*8, ph);
            const float4* vstage = (const float4*)(smem + slot*STAGE_BYTES);
            #pragma unroll
            for (int rr = 0; rr < 2; rr++) {
                int r = rid + rr*2;
                float4 v = vstage[r*XTW + cid];
                unsigned long long v01 = pk2(v.x, v.y);
                unsigned long long v23 = pk2(v.z, v.w);
                const ulonglong2* wr = (const ulonglong2*)&w2s[(j*SROWS + r)*NH + grp*4];
                ulonglong2 wA = wr[0], wB = wr[1];
                fma2(a0[0], v01, wA.x); fma2(a1[0], v23, wA.x);
                fma2(a0[1], v01, wA.y); fma2(a1[1], v23, wA.y);
                fma2(a0[2], v01, wB.x); fma2(a1[2], v23, wB.x);
                fma2(a0[3], v01, wB.y); fma2(a1[3], v23, wB.y);
            }
            __syncthreads();   // slot fully consumed -> safe to refill
            if (tid == 0 && j + STAGES < NSTG)
                issue_stage(sb + ((sc + j + STAGES) & (STAGES-1))*STAGE_BYTES,
                            src + (size_t)(j + STAGES)*SROWS*PIX4,
                            sb + SM_MBAR + ((sc + j + STAGES) & (STAGES-1))*8);
        }
        sc += NSTG;

        int jj = xb*XTW + cid;
        #pragma unroll
        for (int i = 0; i < 4; i++) {
            int h = grp*4 + i;
            float x, y, z, w;
            upk2(a0[i], x, y);
            upk2(a1[i], z, w);
            float* p = (float*)&out4[h*PIX4 + jj];
            asm volatile("red.global.add.v4.f32 [%0], {%1, %2, %3, %4};"
                         :: "l"(p), "f"(x), "f"(y), "f"(z), "f"(w) : "memory");
        }
    }
}

extern "C" void kernel_launch(void* const* d_in, const int* in_sizes, int n_in,
                              void* d_out, int out_size) {
    const float* Q  = (const float*)d_in[0];
    const float* K  = (const float*)d_in[1];
    const float* V  = (const float*)d_in[2];
    const float* WQ = (const float*)d_in[3];
    const float* bQ = (const float*)d_in[4];
    const float* WK = (const float*)d_in[5];
    const float* bK = (const float*)d_in[6];

    prep_kernel<<<PGRID, 256>>>(Q, K, WQ, bQ, WK, bK, (float4*)d_out);
    wsum_kernel<<<WGRID, 256, SM_TOTAL>>>(V, (float4*)d_out);
}

// round 11
// speedup vs baseline: 1.2415x; 1.2415x over previous
#include <cuda_runtime.h>

#define NH 8
#define DD 1024
#define MM 2048
#define PIX4 12288           // 128*128*3 / 4
#define MSLICE 128           // m per wsum tile
#define XTW 128              // float4 columns per wsum tile
#define XT (PIX4/XTW)        // 96
#define NTILES (XT*(MM/MSLICE))   // 96*16 = 1536
#define PGRID 444            // prep grid: 148x3, all-resident even on 148-SM parts
#define WGRID 608            // wsum grid: 152 SMs x 4 (no grid barrier -> safe)
#define NWARPS (PGRID*8)

#define STAGES 4
#define SROWS 4                          // m-rows per stage
#define ROWB (XTW*16)                    // 2048 bytes per row
#define STAGE_BYTES (SROWS*ROWB)         // 8192
#define NSTG (MSLICE/SROWS)              // 32 stages per tile
// dynamic smem layout (wsum)
#define SM_W2S   (STAGES*STAGE_BYTES)    // 32768
#define SM_MBAR  (SM_W2S + MSLICE*NH*8)  // 40960
#define SM_TILE  (SM_MBAR + STAGES*8)    // 40992
#define SM_TOTAL (SM_TILE + 16)          // 41008

__device__ float g_q[NH*DD];
__device__ float g_t[NH*DD];
__device__ float g_c[NH];
__device__ float g_sums[NH];
__device__ float g_wt[MM*NH];   // unnormalized exp weights, transposed [m][h]
__device__ int   g_ctr;         // wsum ticket counter (reset by prep)
__device__ int   g_bar;         // prep grid barrier  (reset by wsum)

__device__ __forceinline__ unsigned long long pk2(float a, float b){
    unsigned long long r;
    asm("mov.b64 %0, {%1, %2};" : "=l"(r) : "f"(a), "f"(b));
    return r;
}
__device__ __forceinline__ void fma2(unsigned long long &acc, unsigned long long v, unsigned long long w){
    asm("fma.rn.f32x2 %0, %1, %2, %0;" : "+l"(acc) : "l"(v), "l"(w));
}
__device__ __forceinline__ void upk2(unsigned long long p, float &a, float &b){
    asm("mov.b64 {%0, %1}, %2;" : "=f"(a), "=f"(b) : "l"(p));
}
__device__ __forceinline__ unsigned int smem_u32(const void* p){
    unsigned int a;
    asm("{ .reg .u64 t; cvta.to.shared.u64 t, %1; cvt.u32.u64 %0, t; }" : "=r"(a) : "l"(p));
    return a;
}
__device__ __forceinline__ void mbar_wait(unsigned int mbar, unsigned int phase){
    asm volatile(
        "{\n\t.reg .pred P;\n"
        "LW%=:\n\t"
        "mbarrier.try_wait.parity.acquire.cta.shared::cta.b64 P, [%0], %1, 0x989680;\n\t"
        "@P bra LD%=;\n\t"
        "bra LW%=;\n"
        "LD%=:\n\t}"
        :: "r"(mbar), "r"(phase) : "memory");
}
// issue one stage: expect_tx + SROWS x 2KB 1D bulk copies (UBLKCP)
__device__ __forceinline__ void issue_stage(unsigned int dst, const float4* src, unsigned int mbar){
    asm volatile("mbarrier.arrive.expect_tx.shared.b64 _, [%0], %1;"
                 :: "r"(mbar), "r"((unsigned)STAGE_BYTES) : "memory");
    #pragma unroll
    for (int r = 0; r < SROWS; r++){
        asm volatile("cp.async.bulk.shared::cluster.global.mbarrier::complete_tx::bytes [%0], [%1], %2, [%3];"
            :: "r"(dst + r*ROWB), "l"(src + (size_t)r*PIX4), "r"((unsigned)ROWB), "r"(mbar)
            : "memory");
    }
}

// Grid barrier for prep: all PGRID blocks resident by construction (444 <= 148*3).
__device__ __forceinline__ void grid_bar(int target) {
    __syncthreads();
    __threadfence();
    if (threadIdx.x == 0) {
        atomicAdd(&g_bar, 1);
        while (*(volatile int*)&g_bar < target) __nanosleep(64);
    }
    __syncthreads();
    __threadfence();
}

// ---------------------------------------------------------------------------
// Fused prologue (R8-proven): 3 phases, 2 grid barriers.
// ---------------------------------------------------------------------------
__global__ void __launch_bounds__(256, 3) prep_kernel(
        const float* __restrict__ Q,  const float* __restrict__ K,
        const float* __restrict__ WQ, const float* __restrict__ bQ,
        const float* __restrict__ WK, const float* __restrict__ bK,
        float4* __restrict__ out4) {
    __shared__ float4 ts4[NH*DD/4];   // 32 KB (phase C)
    __shared__ float ws[8][NH];
    int tid  = threadIdx.x;
    int gid  = blockIdx.x*256 + tid;
    int lane = tid & 31;
    int gwarp = gid >> 5;

    // ---- Phase A ----
    if (gid == 0) g_ctr = 0;
    if (gid < NH*DD) g_t[gid] = 0.f;
    if (gid < NH) { g_c[gid] = 0.f; g_sums[gid] = 0.f; }

    const float4* Q4 = (const float4*)Q;
    for (int task = gwarp; task < NH*DD; task += NWARPS) {
        int h = task >> 10, e = task & 1023;
        const float4* W4 = (const float4*)WQ + (size_t)h*(DD*DD/4) + (size_t)e*(DD/4);
        float acc = 0.f;
        #pragma unroll
        for (int i = 0; i < 8; i++) {
            float4 w = __ldcs(&W4[lane + i*32]);
            float4 q = Q4[lane + i*32];
            acc += w.x*q.x + w.y*q.y + w.z*q.z + w.w*q.w;
        }
        #pragma unroll
        for (int o = 16; o; o >>= 1) acc += __shfl_xor_sync(0xffffffffu, acc, o);
        if (lane == 0) g_q[h*DD + e] = acc + bQ[h*DD + e];
    }
    grid_bar(PGRID);

    // ---- Phase B ---- (1024 block-tasks: (h, e-chunk of 8))
    for (int t = blockIdx.x; t < 1024; t += PGRID) {
        int h = t >> 7, e0 = (t & 127) * 8;
        const float4* Wp = (const float4*)(WK + (size_t)h*DD*DD + (size_t)e0*DD) + tid;
        const float* qp = g_q + h*DD + e0;
        float4 acc = make_float4(0.f, 0.f, 0.f, 0.f);
        #pragma unroll
        for (int e = 0; e < 8; e++) {
            float qe = __ldcg(&qp[e]);
            float4 w = __ldcs(&Wp[(size_t)e*(DD/4)]);
            acc.x = fmaf(qe, w.x, acc.x);
            acc.y = fmaf(qe, w.y, acc.y);
            acc.z = fmaf(qe, w.z, acc.z);
            acc.w = fmaf(qe, w.w, acc.w);
        }
        float* p = &g_t[h*DD + tid*4];
        asm volatile("red.global.add.v4.f32 [%0], {%1, %2, %3, %4};"
                     :: "l"(p), "f"(acc.x), "f"(acc.y), "f"(acc.z), "f"(acc.w) : "memory");
    }
    if (blockIdx.x < 64 && tid < 32) {          // c[h] = q[h] . bK[h]
        int h = blockIdx.x >> 3, e0 = (blockIdx.x & 7) * 128;
        float v = 0.f;
        #pragma unroll
        for (int j = 0; j < 4; j++) {
            int e = e0 + lane + j*32;
            v = fmaf(__ldcg(&g_q[h*DD + e]), bK[h*DD + e], v);
        }
        #pragma unroll
        for (int o = 16; o; o >>= 1) v += __shfl_xor_sync(0xffffffffu, v, o);
        if (lane == 0) atomicAdd(&g_c[h], v);
    }
    grid_bar(2*PGRID);

    // ---- Phase C ----
    for (int idx = gid; idx < NH*PIX4; idx += PGRID*256)
        out4[idx] = make_float4(0.f, 0.f, 0.f, 0.f);

    if (blockIdx.x < 256) {
        for (int i = tid; i < NH*DD/4; i += 256) {
            const float* s = &g_t[i*4];
            ts4[i] = make_float4(__ldcg(s), __ldcg(s+1), __ldcg(s+2), __ldcg(s+3));
        }
        __syncthreads();

        int wid = tid >> 5;
        int m = blockIdx.x * 8 + wid;
        const float4* K4 = (const float4*)K + (size_t)m*(DD/4);
        float acc[NH];
        #pragma unroll
        for (int h = 0; h < NH; h++) acc[h] = 0.f;
        #pragma unroll
        for (int i = 0; i < 8; i++) {
            float4 k4 = K4[lane + i*32];
            #pragma unroll
            for (int h = 0; h < NH; h++) {
                float4 t4 = ts4[h*256 + lane + i*32];
                acc[h] += k4.x*t4.x + k4.y*t4.y + k4.z*t4.z + k4.w*t4.w;
            }
        }
        #pragma unroll
        for (int h = 0; h < NH; h++) {
            #pragma unroll
            for (int o = 16; o; o >>= 1) acc[h] += __shfl_xor_sync(0xffffffffu, acc[h], o);
        }
        if (lane == 0) {
            #pragma unroll
            for (int h = 0; h < NH; h++) {
                float w = expf((acc[h] + __ldcg(&g_c[h])) * (1.0f/1024.0f));
                g_wt[m*NH + h] = w;
                ws[wid][h] = w;
            }
        }
        __syncthreads();
        if (tid < NH) {
            float s = 0.f;
            #pragma unroll
            for (int w8 = 0; w8 < 8; w8++) s += ws[w8][tid];
            atomicAdd(&g_sums[tid], s);
        }
    }
}

// ---------------------------------------------------------------------------
// wsum (R9-proven): persistent tickets; 256KB tiles; cp.async.bulk 4-stage
// smem ring; 2 head-groups x 128 cols; LDS + f32x2 FMA; REDG.v4 output.
// ---------------------------------------------------------------------------
__global__ void __launch_bounds__(256, 4) wsum_kernel(const float* __restrict__ V,
                                                      float4* __restrict__ out4) {
    extern __shared__ char smem[];
    unsigned int sb = smem_u32(smem);
    int tid = threadIdx.x;
    int grp = tid >> 7;          // head group: heads [4g, 4g+4)
    int cid = tid & 127;         // float4 column within tile
    if (blockIdx.x == 0 && tid == 0) g_bar = 0;   // reset prep barrier for next replay

    if (tid == 0) {
        #pragma unroll
        for (int i = 0; i < STAGES; i++)
            asm volatile("mbarrier.init.shared.b64 [%0], 1;" :: "r"(sb + SM_MBAR + i*8) : "memory");
        asm volatile("fence.proxy.async.shared::cta;" ::: "memory");
    }
    __syncthreads();

    unsigned long long* w2s = (unsigned long long*)(smem + SM_W2S);
    int* s_tile = (int*)(smem + SM_TILE);
    int sc = 0;   // absolute stage counter -> slot/parity

    for (;;) {
        if (tid == 0) *s_tile = atomicAdd(&g_ctr, 1);
        __syncthreads();
        int t = *s_tile;
        if (t >= NTILES) break;
        int s  = t / XT;
        int xb = t - s*XT;
        int m0 = s * MSLICE;

        // kick the TMA pipeline FIRST (independent of weights), then fill w2s
        const float4* src = (const float4*)V + (size_t)m0*PIX4 + xb*XTW;
        if (tid == 0) {
            #pragma unroll
            for (int j = 0; j < STAGES; j++)
                issue_stage(sb + ((sc + j) & (STAGES-1))*STAGE_BYTES,
                            src + (size_t)j*SROWS*PIX4,
                            sb + SM_MBAR + ((sc + j) & (STAGES-1))*8);
        }

        for (int i = tid; i < MSLICE*NH; i += 256) {
            float w = __fdividef(g_wt[m0*NH + i], g_sums[i & 7]);
            w2s[i] = pk2(w, w);
        }
        __syncthreads();

        unsigned long long a0[4], a1[4];
        #pragma unroll
        for (int i = 0; i < 4; i++) { a0[i] = 0ull; a1[i] = 0ull; }

        #pragma unroll 1
        for (int j = 0; j < NSTG; j++) {
            int slot = (sc + j) & (STAGES-1);
            unsigned int ph = ((unsigned)(sc + j) >> 2) & 1;
            mbar_wait(sb + SM_MBAR + slot*8, ph);
            const float4* vstage = (const float4*)(smem + slot*STAGE_BYTES);
            #pragma unroll
            for (int r = 0; r < SROWS; r++) {
                float4 v = vstage[r*XTW + cid];
                unsigned long long v01 = pk2(v.x, v.y);
                unsigned long long v23 = pk2(v.z, v.w);
                const ulonglong2* wr = (const ulonglong2*)&w2s[(j*SROWS + r)*NH + grp*4];
                ulonglong2 wA = wr[0], wB = wr[1];
                fma2(a0[0], v01, wA.x); fma2(a1[0], v23, wA.x);
                fma2(a0[1], v01, wA.y); fma2(a1[1], v23, wA.y);
                fma2(a0[2], v01, wB.x); fma2(a1[2], v23, wB.x);
                fma2(a0[3], v01, wB.y); fma2(a1[3], v23, wB.y);
            }
            __syncthreads();   // slot fully consumed -> safe to refill
            if (tid == 0 && j + STAGES < NSTG)
                issue_stage(sb + ((sc + j + STAGES) & (STAGES-1))*STAGE_BYTES,
                            src + (size_t)(j + STAGES)*SROWS*PIX4,
                            sb + SM_MBAR + ((sc + j + STAGES) & (STAGES-1))*8);
        }
        sc += NSTG;

        int jj = xb*XTW + cid;
        #pragma unroll
        for (int i = 0; i < 4; i++) {
            int h = grp*4 + i;
            float x, y, z, w;
            upk2(a0[i], x, y);
            upk2(a1[i], z, w);
            float* p = (float*)&out4[h*PIX4 + jj];
            asm volatile("red.global.add.v4.f32 [%0], {%1, %2, %3, %4};"
                         :: "l"(p), "f"(x), "f"(y), "f"(z), "f"(w) : "memory");
        }
    }
}

extern "C" void kernel_launch(void* const* d_in, const int* in_sizes, int n_in,
                              void* d_out, int out_size) {
    const float* Q  = (const float*)d_in[0];
    const float* K  = (const float*)d_in[1];
    const float* V  = (const float*)d_in[2];
    const float* WQ = (const float*)d_in[3];
    const float* bQ = (const float*)d_in[4];
    const float* WK = (const float*)d_in[5];
    const float* bK = (const float*)d_in[6];

    prep_kernel<<<PGRID, 256>>>(Q, K, WQ, bQ, WK, bK, (float4*)d_out);
    wsum_kernel<<<WGRID, 256, SM_TOTAL>>>(V, (float4*)d_out);
}

// round 12
// speedup vs baseline: 1.2524x; 1.0088x over previous
#include <cuda_runtime.h>

#define NH 8
#define DD 1024
#define MM 2048
#define PIX4 12288           // 128*128*3 / 4
#define MSLICE 128           // m per wsum tile
#define XTW 128              // float4 columns per wsum tile
#define XT (PIX4/XTW)        // 96
#define NTILES (XT*(MM/MSLICE))   // 96*16 = 1536
#define PGRID 592            // prep grid: 148x4, all-resident (grid barrier!)
#define WGRID 608            // wsum grid: 152 SMs x 4 (no grid barrier -> safe)

#define STAGES 4
#define SROWS 4                          // m-rows per stage
#define ROWB (XTW*16)                    // 2048 bytes per row
#define STAGE_BYTES (SROWS*ROWB)         // 8192
#define NSTG (MSLICE/SROWS)              // 32 stages per tile
// dynamic smem layout (wsum)
#define SM_W2S   (STAGES*STAGE_BYTES)    // 32768
#define SM_MBAR  (SM_W2S + MSLICE*NH*8)  // 40960
#define SM_TILE  (SM_MBAR + STAGES*8)    // 40992
#define SM_TOTAL (SM_TILE + 16)          // 41008

// Replay state lifecycle:
//   g_t, g_c : accumulated (REDG/atomic) in prep-AB, read in prep-C,
//              ZEROED IN WSUM (wsum never touches them; module load zeroes run 1)
//   g_sums   : zeroed in prep-AB (pre-barrier), accumulated in prep-C, read in wsum
//   g_wt     : fully overwritten in prep-C, read in wsum
//   g_ctr    : reset in prep, consumed by wsum tickets
//   g_bar    : used by prep barrier, reset in wsum
__device__ float g_t[NH*DD];
__device__ float g_c[NH];
__device__ float g_sums[NH];
__device__ float g_wt[MM*NH];   // unnormalized exp weights, transposed [m][h]
__device__ int   g_ctr;
__device__ int   g_bar;

__device__ __forceinline__ unsigned long long pk2(float a, float b){
    unsigned long long r;
    asm("mov.b64 %0, {%1, %2};" : "=l"(r) : "f"(a), "f"(b));
    return r;
}
__device__ __forceinline__ void fma2(unsigned long long &acc, unsigned long long v, unsigned long long w){
    asm("fma.rn.f32x2 %0, %1, %2, %0;" : "+l"(acc) : "l"(v), "l"(w));
}
__device__ __forceinline__ void upk2(unsigned long long p, float &a, float &b){
    asm("mov.b64 {%0, %1}, %2;" : "=f"(a), "=f"(b) : "l"(p));
}
__device__ __forceinline__ unsigned int smem_u32(const void* p){
    unsigned int a;
    asm("{ .reg .u64 t; cvta.to.shared.u64 t, %1; cvt.u32.u64 %0, t; }" : "=r"(a) : "l"(p));
    return a;
}
__device__ __forceinline__ void mbar_wait(unsigned int mbar, unsigned int phase){
    asm volatile(
        "{\n\t.reg .pred P;\n"
        "LW%=:\n\t"
        "mbarrier.try_wait.parity.acquire.cta.shared::cta.b64 P, [%0], %1, 0x989680;\n\t"
        "@P bra LD%=;\n\t"
        "bra LW%=;\n"
        "LD%=:\n\t}"
        :: "r"(mbar), "r"(phase) : "memory");
}
// issue one stage: expect_tx + SROWS x 2KB 1D bulk copies (UBLKCP)
__device__ __forceinline__ void issue_stage(unsigned int dst, const float4* src, unsigned int mbar){
    asm volatile("mbarrier.arrive.expect_tx.shared.b64 _, [%0], %1;"
                 :: "r"(mbar), "r"((unsigned)STAGE_BYTES) : "memory");
    #pragma unroll
    for (int r = 0; r < SROWS; r++){
        asm volatile("cp.async.bulk.shared::cluster.global.mbarrier::complete_tx::bytes [%0], [%1], %2, [%3];"
            :: "r"(dst + r*ROWB), "l"(src + (size_t)r*PIX4), "r"((unsigned)ROWB), "r"(mbar)
            : "memory");
    }
}

// Grid barrier for prep: all PGRID blocks resident by construction (592 <= 148*4).
__device__ __forceinline__ void grid_bar(int target) {
    __syncthreads();
    __threadfence();
    if (threadIdx.x == 0) {
        atomicAdd(&g_bar, 1);
        while (*(volatile int*)&g_bar < target) __nanosleep(64);
    }
    __syncthreads();
    __threadfence();
}

// ---------------------------------------------------------------------------
// Fused prologue: ONE barrier.
//  Phase AB (task = (h, 8-e-chunk), 1024 tasks):
//    8 warps: q_e = Q.WQ[h,e,:] + bQ[h,e]  -> smem
//    then all 256 threads: t[h,d] += sum_e q_e*WK[h,e,d] (REDG); c[h] += q.bK
//  Phase C: g_wt[m][h] = exp((K[m].t[h] + c[h])/1024); sums; zero d_out.
// ---------------------------------------------------------------------------
__global__ void __launch_bounds__(256, 4) prep_kernel(
        const float* __restrict__ Q,  const float* __restrict__ K,
        const float* __restrict__ WQ, const float* __restrict__ bQ,
        const float* __restrict__ WK, const float* __restrict__ bK,
        float4* __restrict__ out4) {
    __shared__ float4 ts4[NH*DD/4];   // 32 KB (phase C)
    __shared__ float ws[8][NH];
    __shared__ float q_s[8];
    int tid  = threadIdx.x;
    int gid  = blockIdx.x*256 + tid;
    int lane = tid & 31;
    int wid  = tid >> 5;

    // ---- Phase AB ----
    if (gid == 0) g_ctr = 0;
    if (gid < NH) g_sums[gid] = 0.f;

    const float4* Q4 = (const float4*)Q;
    for (int t = blockIdx.x; t < 1024; t += PGRID) {
        int h = t >> 7, e0 = (t & 127) * 8;
        // each warp computes one q_e
        {
            int e = e0 + wid;
            const float4* W4 = (const float4*)WQ + (size_t)h*(DD*DD/4) + (size_t)e*(DD/4);
            float acc = 0.f;
            #pragma unroll
            for (int i = 0; i < 8; i++) {
                float4 w = __ldcs(&W4[lane + i*32]);
                float4 q = Q4[lane + i*32];
                acc += w.x*q.x + w.y*q.y + w.z*q.z + w.w*q.w;
            }
            #pragma unroll
            for (int o = 16; o; o >>= 1) acc += __shfl_xor_sync(0xffffffffu, acc, o);
            if (lane == 0) q_s[wid] = acc + bQ[h*DD + e];
        }
        __syncthreads();

        // c[h] partial from this e-chunk (lanes 0-7 of warp 0)
        if (tid < 8) {
            float v = q_s[tid] * bK[h*DD + e0 + tid];
            v += __shfl_xor_sync(0xffu, v, 4);
            v += __shfl_xor_sync(0xffu, v, 2);
            v += __shfl_xor_sync(0xffu, v, 1);
            if (tid == 0) atomicAdd(&g_c[h], v);
        }

        // t[h,d] partial: all 256 threads, float4 over d
        const float4* Wp = (const float4*)(WK + (size_t)h*DD*DD + (size_t)e0*DD) + tid;
        float4 acc = make_float4(0.f, 0.f, 0.f, 0.f);
        #pragma unroll
        for (int e = 0; e < 8; e++) {
            float qe = q_s[e];
            float4 w = __ldcs(&Wp[(size_t)e*(DD/4)]);
            acc.x = fmaf(qe, w.x, acc.x);
            acc.y = fmaf(qe, w.y, acc.y);
            acc.z = fmaf(qe, w.z, acc.z);
            acc.w = fmaf(qe, w.w, acc.w);
        }
        float* p = &g_t[h*DD + tid*4];
        asm volatile("red.global.add.v4.f32 [%0], {%1, %2, %3, %4};"
                     :: "l"(p), "f"(acc.x), "f"(acc.y), "f"(acc.z), "f"(acc.w) : "memory");
        __syncthreads();   // q_s reused next task
    }
    grid_bar(PGRID);

    // ---- Phase C ----
    for (int idx = gid; idx < NH*PIX4; idx += PGRID*256)
        out4[idx] = make_float4(0.f, 0.f, 0.f, 0.f);

    if (blockIdx.x < 256) {
        for (int i = tid; i < NH*DD/4; i += 256) {
            const float* s = &g_t[i*4];
            ts4[i] = make_float4(__ldcg(s), __ldcg(s+1), __ldcg(s+2), __ldcg(s+3));
        }
        __syncthreads();

        int m = blockIdx.x * 8 + wid;
        const float4* K4 = (const float4*)K + (size_t)m*(DD/4);
        float acc[NH];
        #pragma unroll
        for (int h = 0; h < NH; h++) acc[h] = 0.f;
        #pragma unroll
        for (int i = 0; i < 8; i++) {
            float4 k4 = K4[lane + i*32];
            #pragma unroll
            for (int h = 0; h < NH; h++) {
                float4 t4 = ts4[h*256 + lane + i*32];
                acc[h] += k4.x*t4.x + k4.y*t4.y + k4.z*t4.z + k4.w*t4.w;
            }
        }
        #pragma unroll
        for (int h = 0; h < NH; h++) {
            #pragma unroll
            for (int o = 16; o; o >>= 1) acc[h] += __shfl_xor_sync(0xffffffffu, acc[h], o);
        }
        if (lane == 0) {
            #pragma unroll
            for (int h = 0; h < NH; h++) {
                float w = expf((acc[h] + __ldcg(&g_c[h])) * (1.0f/1024.0f));
                g_wt[m*NH + h] = w;
                ws[wid][h] = w;
            }
        }
        __syncthreads();
        if (tid < NH) {
            float s = 0.f;
            #pragma unroll
            for (int w8 = 0; w8 < 8; w8++) s += ws[w8][tid];
            atomicAdd(&g_sums[tid], s);
        }
    }
}

// ---------------------------------------------------------------------------
// wsum (R9/R11-proven core): persistent tickets; 256KB tiles; cp.async.bulk
// 4-stage smem ring; 2 head-groups x 128 cols; LDS + f32x2 FMA; REDG.v4 out.
// Also zeroes g_t/g_c/g_bar for the next graph replay (safe: untouched here).
// ---------------------------------------------------------------------------
__global__ void __launch_bounds__(256, 4) wsum_kernel(const float* __restrict__ V,
                                                      float4* __restrict__ out4) {
    extern __shared__ char smem[];
    unsigned int sb = smem_u32(smem);
    int tid = threadIdx.x;
    int grp = tid >> 7;          // head group: heads [4g, 4g+4)
    int cid = tid & 127;         // float4 column within tile

    if (blockIdx.x == 0) {       // next-replay state reset (prep completed already)
        if (tid == 0) g_bar = 0;
        if (tid < NH) g_c[tid] = 0.f;
        float4* t4 = (float4*)g_t;
        #pragma unroll
        for (int i = 0; i < NH*DD/4/256; i++)
            t4[i*256 + tid] = make_float4(0.f, 0.f, 0.f, 0.f);
    }

    if (tid == 0) {
        #pragma unroll
        for (int i = 0; i < STAGES; i++)
            asm volatile("mbarrier.init.shared.b64 [%0], 1;" :: "r"(sb + SM_MBAR + i*8) : "memory");
        asm volatile("fence.proxy.async.shared::cta;" ::: "memory");
    }
    __syncthreads();

    // per-block snapshot of normalization factors (8 divides per block total)
    float inv[NH];
    #pragma unroll
    for (int h = 0; h < NH; h++) inv[h] = __fdividef(1.0f, g_sums[h]);

    unsigned long long* w2s = (unsigned long long*)(smem + SM_W2S);
    int* s_tile = (int*)(smem + SM_TILE);
    int sc = 0;   // absolute stage counter -> slot/parity

    for (;;) {
        if (tid == 0) *s_tile = atomicAdd(&g_ctr, 1);
        __syncthreads();
        int t = *s_tile;
        if (t >= NTILES) break;
        int s  = t / XT;
        int xb = t - s*XT;
        int m0 = s * MSLICE;

        // kick the TMA pipeline FIRST (independent of weights), then fill w2s
        const float4* src = (const float4*)V + (size_t)m0*PIX4 + xb*XTW;
        if (tid == 0) {
            #pragma unroll
            for (int j = 0; j < STAGES; j++)
                issue_stage(sb + ((sc + j) & (STAGES-1))*STAGE_BYTES,
                            src + (size_t)j*SROWS*PIX4,
                            sb + SM_MBAR + ((sc + j) & (STAGES-1))*8);
        }

        for (int i = tid; i < MSLICE*NH; i += 256) {
            float w = g_wt[m0*NH + i] * inv[i & 7];
            w2s[i] = pk2(w, w);
        }
        __syncthreads();

        unsigned long long a0[4], a1[4];
        #pragma unroll
        for (int i = 0; i < 4; i++) { a0[i] = 0ull; a1[i] = 0ull; }

        #pragma unroll 1
        for (int j = 0; j < NSTG; j++) {
            int slot = (sc + j) & (STAGES-1);
            unsigned int ph = ((unsigned)(sc + j) >> 2) & 1;
            mbar_wait(sb + SM_MBAR + slot*8, ph);
            const float4* vstage = (const float4*)(smem + slot*STAGE_BYTES);
            #pragma unroll
            for (int r = 0; r < SROWS; r++) {
                float4 v = vstage[r*XTW + cid];
                unsigned long long v01 = pk2(v.x, v.y);
                unsigned long long v23 = pk2(v.z, v.w);
                const ulonglong2* wr = (const ulonglong2*)&w2s[(j*SROWS + r)*NH + grp*4];
                ulonglong2 wA = wr[0], wB = wr[1];
                fma2(a0[0], v01, wA.x); fma2(a1[0], v23, wA.x);
                fma2(a0[1], v01, wA.y); fma2(a1[1], v23, wA.y);
                fma2(a0[2], v01, wB.x); fma2(a1[2], v23, wB.x);
                fma2(a0[3], v01, wB.y); fma2(a1[3], v23, wB.y);
            }
            __syncthreads();   // slot fully consumed -> safe to refill
            if (tid == 0 && j + STAGES < NSTG)
                issue_stage(sb + ((sc + j + STAGES) & (STAGES-1))*STAGE_BYTES,
                            src + (size_t)(j + STAGES)*SROWS*PIX4,
                            sb + SM_MBAR + ((sc + j + STAGES) & (STAGES-1))*8);
        }
        sc += NSTG;

        int jj = xb*XTW + cid;
        #pragma unroll
        for (int i = 0; i < 4; i++) {
            int h = grp*4 + i;
            float x, y, z, w;
            upk2(a0[i], x, y);
            upk2(a1[i], z, w);
            float* p = (float*)&out4[h*PIX4 + jj];
            asm volatile("red.global.add.v4.f32 [%0], {%1, %2, %3, %4};"
                         :: "l"(p), "f"(x), "f"(y), "f"(z), "f"(w) : "memory");
        }
    }
}

extern "C" void kernel_launch(void* const* d_in, const int* in_sizes, int n_in,
                              void* d_out, int out_size) {
    const float* Q  = (const float*)d_in[0];
    const float* K  = (const float*)d_in[1];
    const float* V  = (const float*)d_in[2];
    const float* WQ = (const float*)d_in[3];
    const float* bQ = (const float*)d_in[4];
    const float* WK = (const float*)d_in[5];
    const float* bK = (const float*)d_in[6];

    prep_kernel<<<PGRID, 256>>>(Q, K, WQ, bQ, WK, bK, (float4*)d_out);
    wsum_kernel<<<WGRID, 256, SM_TOTAL>>>(V, (float4*)d_out);
}